// round 11
// baseline (speedup 1.0000x reference)
#include <cuda_runtime.h>
#include <cfloat>

#define PH 7
#define PW 7
#define NN 4
#define CC 128
#define HH 50
#define WW 50
#define SCALE 0.0625f
#define NTILES (256 * PH)

// channel-last features [N][H][W][C], 5.12 MB
__device__ float g_featT[NN * HH * WW * CC];
__device__ int g_ctr;

__global__ void reset_kernel() { g_ctr = 0; }

// transpose [C,W] -> [W,C] per (b,h,c-half)
__global__ void transpose_kernel(const float* __restrict__ feat) {
    int blk = blockIdx.x;
    int b    = blk / (HH * 2);
    int rest = blk % (HH * 2);
    int h    = rest >> 1;
    int c0   = (rest & 1) * 64;

    __shared__ float tile[64 * WW];

    const float* src = feat + ((long)b * CC + c0) * (HH * WW) + h * WW;
    for (int i = threadIdx.x; i < 64 * WW; i += blockDim.x) {
        int c = i / WW;
        int w = i % WW;
        tile[i] = src[(long)c * (HH * WW) + w];
    }
    __syncthreads();
    float* dst = g_featT + ((long)(b * HH + h) * WW) * CC + c0;
    for (int i = threadIdx.x; i < 64 * WW; i += blockDim.x) {
        int w = i >> 6;
        int c = i & 63;
        dst[(long)w * CC + c] = tile[c * WW + w];
    }
}

__device__ __forceinline__ float4 fmax4(float4 a, float4 b) {
    return make_float4(fmaxf(a.x, b.x), fmaxf(a.y, b.y),
                       fmaxf(a.z, b.z), fmaxf(a.w, b.w));
}

// Persistent blocks; tiles = (k, ph) pulled from a global atomic queue.
__global__ __launch_bounds__(256) void roipool_kernel(const float* __restrict__ rois,
                                                      float* __restrict__ out) {
    int tid = threadIdx.x;

    __shared__ float rowmax[WW * CC];   // [w - ws0][c], 25.6 KB
    __shared__ float so[PW * CC];       // [pw][c], 3.5 KB
    __shared__ int s_tile;

    for (;;) {
        if (tid == 0) s_tile = atomicAdd(&g_ctr, 1);
        __syncthreads();
        int tile = s_tile;
        if (tile >= NTILES) return;
        int k  = tile / PH;
        int ph = tile % PH;

        const float* r = rois + k * 5;
        int b  = (int)__ldg(r + 0);
        int x1 = (int)rintf(__ldg(r + 1) * SCALE);
        int y1 = (int)rintf(__ldg(r + 2) * SCALE);
        int x2 = (int)rintf(__ldg(r + 3) * SCALE);
        int y2 = (int)rintf(__ldg(r + 4) * SCALE);

        int roi_wi = max(x2 - x1 + 1, 1);
        int roi_hi = max(y2 - y1 + 1, 1);
        float bw = (float)roi_wi * (1.0f / PW);
        float bh = (float)roi_hi * (1.0f / PH);

        int hs = min(max((int)floorf((float)ph * bh) + y1, 0), HH);
        int he = min(max((int)ceilf((float)(ph + 1) * bh) + y1, 0), HH);

        // w band covering all pw bins, same formulas as the bins themselves
        int ws0 = min(max(x1, 0), WW);
        int we6 = min(max((int)ceilf((float)PW * bw) + x1, 0), WW);
        int cnt = we6 - ws0;

        // ---- Phase 1: h-reduce each w column (warp = w chunk, lane = 4ch) ----
        if (he > hs) {
            int wc   = tid >> 5;   // 0..7
            int lane = tid & 31;
            const float4* fb = reinterpret_cast<const float4*>(
                g_featT + ((long)b * HH * WW) * CC) + lane;
            for (int w = wc; w < cnt; w += 8) {
                const float4* col = fb + (long)(ws0 + w) * (CC / 4);
                float4 m = make_float4(-FLT_MAX, -FLT_MAX, -FLT_MAX, -FLT_MAX);
                int h = hs;
                for (; h + 1 < he; h += 2) {
                    float4 a  = __ldg(col + (long)(h * WW) * (CC / 4));
                    float4 b4 = __ldg(col + (long)((h + 1) * WW) * (CC / 4));
                    m = fmax4(m, fmax4(a, b4));
                }
                if (h < he) {
                    float4 a = __ldg(col + (long)(h * WW) * (CC / 4));
                    m = fmax4(m, a);
                }
                reinterpret_cast<float4*>(rowmax + w * CC)[lane] = m;
            }
        }
        __syncthreads();

        // ---- Phase 2: w-reduce per pw bin from smem (float4 lanes) ----
        if (tid < PW * 32) {
            int pw = tid >> 5;
            int cp = tid & 31;
            int ws = min(max((int)floorf((float)pw * bw) + x1, 0), WW);
            int we = min(max((int)ceilf((float)(pw + 1) * bw) + x1, 0), WW);
            bool empty = (he <= hs) || (we <= ws);

            float4 m = make_float4(-FLT_MAX, -FLT_MAX, -FLT_MAX, -FLT_MAX);
            if (!empty) {
                for (int w = ws; w < we; w++) {
                    float4 v = reinterpret_cast<const float4*>(
                        rowmax + (w - ws0) * CC)[cp];
                    m = fmax4(m, v);
                }
            } else {
                m = make_float4(0.f, 0.f, 0.f, 0.f);
            }
            reinterpret_cast<float4*>(so + pw * CC)[cp] = m;
        }
        __syncthreads();

        // ---- staged output: out[k][c][ph][pw] ----
        float* ok = out + (long)k * (CC * PH * PW) + ph * PW;
        for (int e = tid; e < CC * PW; e += 256) {
            int cc  = e / PW;
            int ppw = e % PW;
            ok[cc * (PH * PW) + ppw] = so[ppw * CC + cc];
        }
        __syncthreads();   // protect smem reuse next iteration
    }
}

extern "C" void kernel_launch(void* const* d_in, const int* in_sizes, int n_in,
                              void* d_out, int out_size) {
    const float* feat = (const float*)d_in[0];
    const float* rois = (const float*)d_in[1];
    float* out = (float*)d_out;

    static bool attr_done = false;
    if (!attr_done) {
        cudaFuncSetAttribute(roipool_kernel,
                             cudaFuncAttributePreferredSharedMemoryCarveout, 100);
        attr_done = true;
    }

    reset_kernel<<<1, 1>>>();
    transpose_kernel<<<NN * HH * 2, 256>>>(feat);
    roipool_kernel<<<1036, 256>>>(rois, out);
}

// round 14
// speedup vs baseline: 1.1081x; 1.1081x over previous
#include <cuda_runtime.h>
#include <cfloat>

#define PH 7
#define PW 7
#define NN 4
#define CC 128
#define HH 50
#define WW 50
#define SCALE 0.0625f

// channel-last features [N][H][W][C], 5.12 MB
__device__ float g_featT[NN * HH * WW * CC];

// transpose [C,W] -> [W,C] per (b,h,c-half)
__global__ void transpose_kernel(const float* __restrict__ feat) {
    int blk = blockIdx.x;
    int b    = blk / (HH * 2);
    int rest = blk % (HH * 2);
    int h    = rest >> 1;
    int c0   = (rest & 1) * 64;

    __shared__ float tile[64 * WW];

    // read 64 rows of 50 floats as 25 float2 each (1600 float2, 256 threads)
    const float* src = feat + ((long)b * CC + c0) * (HH * WW) + h * WW;
    for (int i = threadIdx.x; i < 64 * 25; i += blockDim.x) {
        int c  = i / 25;
        int w2 = i % 25;
        float2 v = *reinterpret_cast<const float2*>(src + (long)c * (HH * WW) + w2 * 2);
        tile[c * WW + w2 * 2]     = v.x;
        tile[c * WW + w2 * 2 + 1] = v.y;
    }
    __syncthreads();
    float* dst = g_featT + ((long)(b * HH + h) * WW) * CC + c0;
    for (int i = threadIdx.x; i < 64 * WW; i += blockDim.x) {
        int w = i >> 6;
        int c = i & 63;
        dst[(long)w * CC + c] = tile[c * WW + w];
    }
}

__device__ __forceinline__ float4 fmax4(float4 a, float4 b) {
    return make_float4(fmaxf(a.x, b.x), fmaxf(a.y, b.y),
                       fmaxf(a.z, b.z), fmaxf(a.w, b.w));
}

// One block (256 thr) per (k, ph). Phase 1: h-reduce w columns into smem,
// TWO columns per warp-iteration for MLP=4. Phase 2: w-reduce per pw bin.
__global__ __launch_bounds__(256) void roipool_kernel(const float* __restrict__ rois,
                                                      float* __restrict__ out) {
    int k  = blockIdx.x / PH;
    int ph = blockIdx.x % PH;
    int tid = threadIdx.x;

    __shared__ float rowmax[WW * CC];   // [w - ws0][c], 25.6 KB
    __shared__ float so[PW * CC];       // [pw][c], 3.5 KB

    const float* r = rois + k * 5;
    int b  = (int)__ldg(r + 0);
    int x1 = (int)rintf(__ldg(r + 1) * SCALE);
    int y1 = (int)rintf(__ldg(r + 2) * SCALE);
    int x2 = (int)rintf(__ldg(r + 3) * SCALE);
    int y2 = (int)rintf(__ldg(r + 4) * SCALE);

    int roi_wi = max(x2 - x1 + 1, 1);
    int roi_hi = max(y2 - y1 + 1, 1);
    float bw = (float)roi_wi * (1.0f / PW);
    float bh = (float)roi_hi * (1.0f / PH);

    int hs = min(max((int)floorf((float)ph * bh) + y1, 0), HH);
    int he = min(max((int)ceilf((float)(ph + 1) * bh) + y1, 0), HH);

    // w band covering all pw bins, same formulas as the bins themselves
    int ws0 = min(max(x1, 0), WW);
    int we6 = min(max((int)ceilf((float)PW * bw) + x1, 0), WW);
    int cnt = we6 - ws0;

    // ---- Phase 1: h-reduce columns; 2 columns/warp-iter (MLP=4) ----
    if (he > hs) {
        int wc   = tid >> 5;   // 0..7
        int lane = tid & 31;
        const float4* fb = reinterpret_cast<const float4*>(
            g_featT + ((long)b * HH * WW) * CC) + lane;
        for (int w = wc; w < cnt; w += 16) {
            int wB = w + 8;
            bool has2 = wB < cnt;
            int wBc = has2 ? wB : w;
            const float4* colA = fb + (long)(ws0 + w)   * (CC / 4);
            const float4* colB = fb + (long)(ws0 + wBc) * (CC / 4);
            float4 mA = make_float4(-FLT_MAX, -FLT_MAX, -FLT_MAX, -FLT_MAX);
            float4 mB = mA;
            int h = hs;
            for (; h + 1 < he; h += 2) {
                long o0 = (long)(h * WW) * (CC / 4);
                long o1 = (long)((h + 1) * WW) * (CC / 4);
                float4 a0 = __ldg(colA + o0);
                float4 b0 = __ldg(colB + o0);
                float4 a1 = __ldg(colA + o1);
                float4 b1 = __ldg(colB + o1);
                mA = fmax4(mA, fmax4(a0, a1));
                mB = fmax4(mB, fmax4(b0, b1));
            }
            if (h < he) {
                long o0 = (long)(h * WW) * (CC / 4);
                float4 a0 = __ldg(colA + o0);
                float4 b0 = __ldg(colB + o0);
                mA = fmax4(mA, a0);
                mB = fmax4(mB, b0);
            }
            reinterpret_cast<float4*>(rowmax + w * CC)[lane] = mA;
            if (has2)
                reinterpret_cast<float4*>(rowmax + wB * CC)[lane] = mB;
        }
    }
    __syncthreads();

    // ---- Phase 2: w-reduce per pw bin from smem (float4 lanes) ----
    if (tid < PW * 32) {
        int pw = tid >> 5;
        int cp = tid & 31;
        int ws = min(max((int)floorf((float)pw * bw) + x1, 0), WW);
        int we = min(max((int)ceilf((float)(pw + 1) * bw) + x1, 0), WW);
        bool empty = (he <= hs) || (we <= ws);

        float4 m = make_float4(-FLT_MAX, -FLT_MAX, -FLT_MAX, -FLT_MAX);
        if (!empty) {
            for (int w = ws; w < we; w++) {
                float4 v = reinterpret_cast<const float4*>(
                    rowmax + (w - ws0) * CC)[cp];
                m = fmax4(m, v);
            }
        } else {
            m = make_float4(0.f, 0.f, 0.f, 0.f);
        }
        reinterpret_cast<float4*>(so + pw * CC)[cp] = m;
    }
    __syncthreads();

    // ---- staged output: out[k][c][ph][pw] ----
    float* ok = out + (long)k * (CC * PH * PW) + ph * PW;
    for (int e = tid; e < CC * PW; e += 256) {
        int cc  = e / PW;
        int ppw = e % PW;
        ok[cc * (PH * PW) + ppw] = so[ppw * CC + cc];
    }
}

extern "C" void kernel_launch(void* const* d_in, const int* in_sizes, int n_in,
                              void* d_out, int out_size) {
    const float* feat = (const float*)d_in[0];
    const float* rois = (const float*)d_in[1];
    float* out = (float*)d_out;
    int K = in_sizes[1] / 5;  // 256

    static bool attr_done = false;
    if (!attr_done) {
        cudaFuncSetAttribute(roipool_kernel,
                             cudaFuncAttributePreferredSharedMemoryCarveout, 100);
        attr_done = true;
    }

    transpose_kernel<<<NN * HH * 2, 256>>>(feat);
    roipool_kernel<<<K * PH, 256>>>(rois, out);
}